// round 9
// baseline (speedup 1.0000x reference)
#include <cuda_runtime.h>
#include <cstdint>
#include <cstddef>

// ---------------- Problem constants ----------------
#define BB   8
#define NN   1024
#define DIMC 512
#define HH   8
#define DD   64
#define RR   64          // R1 = R2 = R = 64
#define MTOT (BB*NN)     // 8192
#define SCALE_ATT 0.125f // D^-0.5
#define S_CONST 1.0f

// ---------------- Scratch (__device__ globals; no allocation allowed) ----------------
__device__ float g_qkv  [(size_t)MTOT*3*DIMC];
__device__ float g_att  [(size_t)MTOT*DIMC];
__device__ float g_CPc  [4*RR*RR];          // [f][ij]  (f-major for contiguous wfac reads)
__device__ float g_WbigT[3*DIMC*RR];        // [o][r] o in [0,1536)
__device__ float g_WpT  [DIMC*RR];          // [d][r] (pre-scaled by S)
__device__ float g_Wcq  [(size_t)3*DIMC*DIMC]; // [o][c] = qkv_w + WbigT@CP_U_w
__device__ float g_Wcp  [DIMC*DIMC];           // [o][c] = proj_w + WpT@CP_U_w
__device__ float g_bqc  [3*DIMC];           // CP_V_b(tiled) + CP_U_b@Wbig
__device__ float g_bpc  [DIMC];             // proj_b + S*CP_V_b + CP_U_b@Wp

// ---------------- Small precompute kernels ----------------
// CPc[f][ij] = sum_r CP_C[ij][r] * CP_att[r][f];  16 blocks x 256 thr, 1 thr/ij
__global__ void cpc_kernel(const float* __restrict__ CP_C, const float* __restrict__ CP_att) {
    __shared__ float att_s[RR * 4];
    int tid = threadIdx.x;
    att_s[tid] = CP_att[tid];                 // 256 = 64*4 exactly
    __syncthreads();
    int ij = blockIdx.x * 256 + tid;          // 0..4095
    const float4* row = (const float4*)&CP_C[(size_t)ij << 6];
    float a0 = 0.f, a1 = 0.f, a2 = 0.f, a3 = 0.f;
    #pragma unroll
    for (int r4 = 0; r4 < 16; r4++) {
        float4 v = row[r4];
        const float* at = &att_s[r4 * 16];
        a0 += v.x * at[0]  + v.y * at[4]  + v.z * at[8]  + v.w * at[12];
        a1 += v.x * at[1]  + v.y * at[5]  + v.z * at[9]  + v.w * at[13];
        a2 += v.x * at[2]  + v.y * at[6]  + v.z * at[10] + v.w * at[14];
        a3 += v.x * at[3]  + v.y * at[7]  + v.z * at[11] + v.w * at[15];
    }
    g_CPc[0 * 4096 + ij] = a0;
    g_CPc[1 * 4096 + ij] = a1;
    g_CPc[2 * 4096 + ij] = a2;
    g_CPc[3 * 4096 + ij] = a3;
}

// WbigT[o][r] / WpT[d][r] = sum_s CPc[f][r*64+s] * CP_V_w[d][s]
// 512 blocks x 256 thr; r = idx&63, o = idx>>6  (coalesced stores)
__global__ void wfac_kernel(const float* __restrict__ CP_V_w) {
    int idx = blockIdx.x * 256 + threadIdx.x;   // 131072
    int r = idx & 63;
    int o = idx >> 6;                           // 0..2047
    int f, d;
    if (o < 3 * DIMC) { f = o >> 9; d = o & 511; }
    else              { f = 3;      d = o - 3 * DIMC; }
    const float4* cp = (const float4*)&g_CPc[f * 4096 + r * RR];
    const float4* vw = (const float4*)&CP_V_w[(size_t)d * RR];
    float s = 0.f;
    #pragma unroll
    for (int i = 0; i < 16; i++) {
        float4 a = cp[i], b = vw[i];
        s += a.x * b.x + a.y * b.y + a.z * b.z + a.w * b.w;
    }
    if (o < 3 * DIMC) g_WbigT[o * RR + r] = s;
    else              g_WpT[d * RR + r] = s * S_CONST;
}

// bqc[i] = CP_V_b[i&511] + CP_U_b@WbigT[i,:]   (i<1536)
// bpc[d] = proj_b[d] + S*CP_V_b[d] + CP_U_b@WpT[d,:]
// warp-per-output: 256 blocks x 256 thr = 2048 warps
__global__ void biascomb_kernel(const float* __restrict__ CP_U_b,
                                const float* __restrict__ CP_V_b,
                                const float* __restrict__ proj_b) {
    int w = blockIdx.x * 8 + (threadIdx.x >> 5);  // 0..2047
    int lane = threadIdx.x & 31;
    const float* row = (w < 3 * DIMC) ? &g_WbigT[w * RR] : &g_WpT[(w - 3 * DIMC) * RR];
    float s = CP_U_b[lane] * row[lane] + CP_U_b[lane + 32] * row[lane + 32];
    #pragma unroll
    for (int off = 16; off > 0; off >>= 1)
        s += __shfl_down_sync(0xffffffffu, s, off);
    if (lane == 0) {
        if (w < 3 * DIMC) g_bqc[w] = CP_V_b[w & 511] + s;
        else {
            int d = w - 3 * DIMC;
            g_bpc[d] = proj_b[d] + S_CONST * CP_V_b[d] + s;
        }
    }
}

// ---------------- tf32 helpers ----------------
__device__ __forceinline__ uint32_t f2tf(float x) {
    uint32_t r;
    asm("cvt.rna.tf32.f32 %0, %1;" : "=r"(r) : "f"(x));
    return r;
}

__device__ __forceinline__ void mma_tf32(float c[4], uint32_t a0, uint32_t a1,
                                         uint32_t a2, uint32_t a3,
                                         uint32_t b0, uint32_t b1) {
    asm volatile(
        "mma.sync.aligned.m16n8k8.row.col.f32.tf32.tf32.f32 "
        "{%0,%1,%2,%3}, {%4,%5,%6,%7}, {%8,%9}, {%0,%1,%2,%3};\n"
        : "+f"(c[0]), "+f"(c[1]), "+f"(c[2]), "+f"(c[3])
        : "r"(a0), "r"(a1), "r"(a2), "r"(a3), "r"(b0), "r"(b1));
}

// Shared dynamic-smem symbol (aliased by both gemm and attention kernels)
extern __shared__ float att_sm[];

// ---------------- Double-buffered tf32 GEMM, warp tile 64x64 ----------------
// C[M,N] = A[M,K]@B (+ bias[N]) (+ Cadd[M,N])
// BNK=1: B stored [N,K] row-major (weights). BNK=0: B stored [K,N] row-major.
// BM=128, BN=256, BK=16, 256 thr (8 warps: 2m x 4n), warp tile 64x64.
// Dynamic smem: As[2][128][20] + Bs[2][256][20] uint32 = 61440 bytes.
#define GEMM_SMEM_BYTES ((2*128*20 + 2*256*20) * 4)
#define AS(p, r, c) As[((p) * 128 + (r)) * 20 + (c)]
#define BS(p, n, c) Bs[((p) * 256 + (n)) * 20 + (c)]

template<int BNK>
__global__ __launch_bounds__(256)
void gemm_tf32(const float* __restrict__ A, int lda,
               const float* __restrict__ B, int K,
               const float* __restrict__ bias, const float* __restrict__ Cadd,
               float* __restrict__ C, int N) {
    uint32_t* As = (uint32_t*)att_sm;
    uint32_t* Bs = As + 2 * 128 * 20;

    int tid  = threadIdx.x;
    int lane = tid & 31;
    int warp = tid >> 5;
    int warp_m = (warp & 1) * 64;
    int warp_n = (warp >> 1) * 64;
    int bm0 = blockIdx.y * 128;
    int bn0 = blockIdx.x * 256;
    int lr = lane >> 2;
    int lc = lane & 3;

    float acc[4][8][4];
    #pragma unroll
    for (int i = 0; i < 4; i++)
        #pragma unroll
        for (int j = 0; j < 8; j++)
            #pragma unroll
            for (int k = 0; k < 4; k++) acc[i][j][k] = 0.f;

    // A loader: rows a_m, a_m+64; k offset a_k
    int a_m = tid >> 2;                // 0..63
    int a_k = (tid & 3) * 4;           // 0,4,8,12
    const float* pa0 = &A[(size_t)(bm0 + a_m) * lda + a_k];
    const float* pa1 = &A[(size_t)(bm0 + a_m + 64) * lda + a_k];

    // B loader
    int bkn_k = tid >> 4;              // KN: 0..15
    int bkn_n = (tid & 15) * 16;       // KN: 0..240
    const float* pb_kn = &B[(size_t)bkn_k * N + bn0 + bkn_n];
    const float* pb_nk = &B[(size_t)(bn0 + tid) * K];   // NK: full row of 16 per thread

    float4 av0, av1, bv[4];

    // ---- prologue: load + store tile 0 ----
    av0 = *(const float4*)pa0;
    av1 = *(const float4*)pa1;
    if (BNK) {
        #pragma unroll
        for (int i = 0; i < 4; i++) bv[i] = *(const float4*)(pb_nk + i * 4);
    } else {
        #pragma unroll
        for (int i = 0; i < 4; i++) bv[i] = *(const float4*)(pb_kn + i * 4);
    }
    {
        uint4 wa0 = make_uint4(f2tf(av0.x), f2tf(av0.y), f2tf(av0.z), f2tf(av0.w));
        uint4 wa1 = make_uint4(f2tf(av1.x), f2tf(av1.y), f2tf(av1.z), f2tf(av1.w));
        *(uint4*)&AS(0, a_m, a_k)      = wa0;
        *(uint4*)&AS(0, a_m + 64, a_k) = wa1;
        if (BNK) {
            #pragma unroll
            for (int i = 0; i < 4; i++) {
                uint4 wb = make_uint4(f2tf(bv[i].x), f2tf(bv[i].y), f2tf(bv[i].z), f2tf(bv[i].w));
                *(uint4*)&BS(0, tid, i * 4) = wb;
            }
        } else {
            #pragma unroll
            for (int i = 0; i < 4; i++) {
                BS(0, bkn_n + i * 4 + 0, bkn_k) = f2tf(bv[i].x);
                BS(0, bkn_n + i * 4 + 1, bkn_k) = f2tf(bv[i].y);
                BS(0, bkn_n + i * 4 + 2, bkn_k) = f2tf(bv[i].z);
                BS(0, bkn_n + i * 4 + 3, bkn_k) = f2tf(bv[i].w);
            }
        }
    }
    __syncthreads();

    int T = K / 16;
    #pragma unroll 1
    for (int t = 0; t < T; t++) {
        int p = t & 1;
        // prefetch next tile (LDG) — hides under mma stage below
        if (t + 1 < T) {
            int k0 = (t + 1) * 16;
            av0 = *(const float4*)(pa0 + k0);
            av1 = *(const float4*)(pa1 + k0);
            if (BNK) {
                #pragma unroll
                for (int i = 0; i < 4; i++) bv[i] = *(const float4*)(pb_nk + k0 + i * 4);
            } else {
                #pragma unroll
                for (int i = 0; i < 4; i++)
                    bv[i] = *(const float4*)(pb_kn + (size_t)k0 * N + i * 4);
            }
        }

        // ---- mma on buffer p ----
        #pragma unroll
        for (int kk = 0; kk < 16; kk += 8) {
            uint32_t af[4][4], bf[8][2];
            #pragma unroll
            for (int mt = 0; mt < 4; mt++) {
                int r = warp_m + mt * 16 + lr;
                af[mt][0] = AS(p, r, kk + lc);
                af[mt][1] = AS(p, r + 8, kk + lc);
                af[mt][2] = AS(p, r, kk + 4 + lc);
                af[mt][3] = AS(p, r + 8, kk + 4 + lc);
            }
            #pragma unroll
            for (int nt = 0; nt < 8; nt++) {
                int c = warp_n + nt * 8 + lr;
                bf[nt][0] = BS(p, c, kk + lc);
                bf[nt][1] = BS(p, c, kk + 4 + lc);
            }
            #pragma unroll
            for (int mt = 0; mt < 4; mt++)
                #pragma unroll
                for (int nt = 0; nt < 8; nt++)
                    mma_tf32(acc[mt][nt], af[mt][0], af[mt][1], af[mt][2], af[mt][3],
                             bf[nt][0], bf[nt][1]);
        }

        // ---- store next tile into the other buffer ----
        if (t + 1 < T) {
            int q = 1 - p;
            uint4 wa0 = make_uint4(f2tf(av0.x), f2tf(av0.y), f2tf(av0.z), f2tf(av0.w));
            uint4 wa1 = make_uint4(f2tf(av1.x), f2tf(av1.y), f2tf(av1.z), f2tf(av1.w));
            *(uint4*)&AS(q, a_m, a_k)      = wa0;
            *(uint4*)&AS(q, a_m + 64, a_k) = wa1;
            if (BNK) {
                #pragma unroll
                for (int i = 0; i < 4; i++) {
                    uint4 wb = make_uint4(f2tf(bv[i].x), f2tf(bv[i].y), f2tf(bv[i].z), f2tf(bv[i].w));
                    *(uint4*)&BS(q, tid, i * 4) = wb;
                }
            } else {
                #pragma unroll
                for (int i = 0; i < 4; i++) {
                    BS(q, bkn_n + i * 4 + 0, bkn_k) = f2tf(bv[i].x);
                    BS(q, bkn_n + i * 4 + 1, bkn_k) = f2tf(bv[i].y);
                    BS(q, bkn_n + i * 4 + 2, bkn_k) = f2tf(bv[i].z);
                    BS(q, bkn_n + i * 4 + 3, bkn_k) = f2tf(bv[i].w);
                }
            }
        }
        __syncthreads();
    }

    // Epilogue: optional bias + optional matrix add + store
    #pragma unroll
    for (int mt = 0; mt < 4; mt++) {
        int row = bm0 + warp_m + mt * 16 + lr;
        #pragma unroll
        for (int nt = 0; nt < 8; nt++) {
            int col = bn0 + warp_n + nt * 8 + lc * 2;
            float b0 = 0.f, b1 = 0.f;
            if (bias) { b0 = bias[col]; b1 = bias[col + 1]; }
            float2 v0 = make_float2(acc[mt][nt][0] + b0, acc[mt][nt][1] + b1);
            float2 v1 = make_float2(acc[mt][nt][2] + b0, acc[mt][nt][3] + b1);
            if (Cadd) {
                float2 c0 = *(const float2*)&Cadd[(size_t)row * N + col];
                float2 c1 = *(const float2*)&Cadd[(size_t)(row + 8) * N + col];
                v0.x += c0.x; v0.y += c0.y;
                v1.x += c1.x; v1.y += c1.y;
            }
            *(float2*)&C[(size_t)row * N + col] = v0;
            *(float2*)&C[(size_t)(row + 8) * N + col] = v1;
        }
    }
}

// ---------------- Tensor-core flash attention (tf32 mma, fp32 softmax) ----------------
#define SP_STRIDE 68
#define KS_STRIDE 68
#define VS_STRIDE 72
#define ATT_SP_OFF   0
#define ATT_KS_OFF   (128*SP_STRIDE)
#define ATT_VS_OFF   (ATT_KS_OFF + 64*KS_STRIDE)
#define ATT_MA_OFF   (ATT_VS_OFF + 64*VS_STRIDE)
#define ATT_FAC_OFF  (ATT_MA_OFF + 64)
#define ATT_SMEM_FLOATS (ATT_FAC_OFF + 128)
#define ATT_SMEM_BYTES  (ATT_SMEM_FLOATS * 4)

__global__ __launch_bounds__(256, 2)
void attn_mma_kernel(const float* __restrict__ qkv, const int* __restrict__ mask,
                     float* __restrict__ out) {
    float*    SP   = att_sm + ATT_SP_OFF;
    float*    Ks   = att_sm + ATT_KS_OFF;
    float*    Vs   = att_sm + ATT_VS_OFF;
    float*    ma   = att_sm + ATT_MA_OFF;
    float*    facs = att_sm + ATT_FAC_OFF;
    uint32_t* SPu  = (uint32_t*)SP;
    uint32_t* Ksu  = (uint32_t*)Ks;
    uint32_t* Vsu  = (uint32_t*)Vs;

    int tid = threadIdx.x, lane = tid & 31, warp = tid >> 5;
    int b = blockIdx.z, h = blockIdx.y;
    int brow = blockIdx.x * 128;
    int g = lane >> 2, tg = lane & 3;
    int wr = warp * 16;
    int row_l = lane >> 1, half = lane & 1;

    {
        int row = tid >> 1, hf = tid & 1;
        const float* qp = qkv + ((size_t)(b * NN + brow + row)) * (3 * DIMC) + h * DD + hf * 32;
        uint32_t* dst = SPu + row * SP_STRIDE + hf * 32;
        #pragma unroll
        for (int i = 0; i < 8; i++) {
            float4 v = *(const float4*)(qp + i * 4);
            dst[i * 4 + 0] = f2tf(v.x * SCALE_ATT);
            dst[i * 4 + 1] = f2tf(v.y * SCALE_ATT);
            dst[i * 4 + 2] = f2tf(v.z * SCALE_ATT);
            dst[i * 4 + 3] = f2tf(v.w * SCALE_ATT);
        }
    }
    __syncthreads();

    uint32_t aq[8][4];
    #pragma unroll
    for (int kk = 0; kk < 8; kk++) {
        aq[kk][0] = SPu[(wr + g) * SP_STRIDE + kk * 8 + tg];
        aq[kk][1] = SPu[(wr + g + 8) * SP_STRIDE + kk * 8 + tg];
        aq[kk][2] = SPu[(wr + g) * SP_STRIDE + kk * 8 + 4 + tg];
        aq[kk][3] = SPu[(wr + g + 8) * SP_STRIDE + kk * 8 + 4 + tg];
    }

    float o[8][4];
    #pragma unroll
    for (int nt = 0; nt < 8; nt++)
        #pragma unroll
        for (int i = 0; i < 4; i++) o[nt][i] = 0.f;
    float m_run = -1e30f, l_run = 0.f;

    #pragma unroll 1
    for (int t = 0; t < NN / 64; t++) {
        int k0 = t * 64;
        __syncthreads();
        {
            int r = tid >> 2, c4 = (tid & 3) * 16;
            size_t base = ((size_t)(b * NN + k0 + r)) * (3 * DIMC) + h * DD + c4;
            const float* kp = qkv + base + DIMC;
            const float* vp = qkv + base + 2 * DIMC;
            uint32_t* kd = Ksu + r * KS_STRIDE + c4;
            uint32_t* vd = Vsu + r * VS_STRIDE + c4;
            #pragma unroll
            for (int i = 0; i < 4; i++) {
                float4 kv = *(const float4*)(kp + i * 4);
                float4 vv = *(const float4*)(vp + i * 4);
                kd[i * 4 + 0] = f2tf(kv.x);
                kd[i * 4 + 1] = f2tf(kv.y);
                kd[i * 4 + 2] = f2tf(kv.z);
                kd[i * 4 + 3] = f2tf(kv.w);
                vd[i * 4 + 0] = f2tf(vv.x);
                vd[i * 4 + 1] = f2tf(vv.y);
                vd[i * 4 + 2] = f2tf(vv.z);
                vd[i * 4 + 3] = f2tf(vv.w);
            }
            if (tid < 64) ma[tid] = mask[b * NN + k0 + tid] ? 0.f : -1e30f;
        }
        __syncthreads();

        float s[8][4];
        #pragma unroll
        for (int nt = 0; nt < 8; nt++)
            #pragma unroll
            for (int i = 0; i < 4; i++) s[nt][i] = 0.f;
        #pragma unroll
        for (int kk = 0; kk < 8; kk++) {
            #pragma unroll
            for (int nt = 0; nt < 8; nt++) {
                uint32_t b0 = Ksu[(nt * 8 + g) * KS_STRIDE + kk * 8 + tg];
                uint32_t b1 = Ksu[(nt * 8 + g) * KS_STRIDE + kk * 8 + 4 + tg];
                mma_tf32(s[nt], aq[kk][0], aq[kk][1], aq[kk][2], aq[kk][3], b0, b1);
            }
        }
        #pragma unroll
        for (int nt = 0; nt < 8; nt++) {
            *(float2*)&SP[(wr + g) * SP_STRIDE + nt * 8 + 2 * tg]     = make_float2(s[nt][0], s[nt][1]);
            *(float2*)&SP[(wr + g + 8) * SP_STRIDE + nt * 8 + 2 * tg] = make_float2(s[nt][2], s[nt][3]);
        }
        __syncwarp();

        {
            float* srow = SP + (wr + row_l) * SP_STRIDE + half * 32;
            const float* mrow = ma + half * 32;
            float tm = -1e30f;
            #pragma unroll
            for (int j = 0; j < 32; j++) tm = fmaxf(tm, srow[j] + mrow[j]);
            tm = fmaxf(tm, __shfl_xor_sync(0xffffffffu, tm, 1));
            float m_new = fmaxf(m_run, tm);
            float fac = __expf(m_run - m_new);
            float ps = 0.f;
            uint32_t* prow = SPu + (wr + row_l) * SP_STRIDE + half * 32;
            #pragma unroll
            for (int j = 0; j < 32; j++) {
                float p = __expf(srow[j] + mrow[j] - m_new);
                ps += p;
                prow[j] = f2tf(p);
            }
            ps += __shfl_xor_sync(0xffffffffu, ps, 1);
            l_run = l_run * fac + ps;
            m_run = m_new;
            if (half == 0) facs[wr + row_l] = fac;
        }
        __syncwarp();

        float fg  = facs[wr + g];
        float fg8 = facs[wr + g + 8];
        #pragma unroll
        for (int nt = 0; nt < 8; nt++) {
            o[nt][0] *= fg;  o[nt][1] *= fg;
            o[nt][2] *= fg8; o[nt][3] *= fg8;
        }
        #pragma unroll
        for (int kk = 0; kk < 8; kk++) {
            uint32_t a0 = SPu[(wr + g) * SP_STRIDE + kk * 8 + tg];
            uint32_t a1 = SPu[(wr + g + 8) * SP_STRIDE + kk * 8 + tg];
            uint32_t a2 = SPu[(wr + g) * SP_STRIDE + kk * 8 + 4 + tg];
            uint32_t a3 = SPu[(wr + g + 8) * SP_STRIDE + kk * 8 + 4 + tg];
            #pragma unroll
            for (int nt = 0; nt < 8; nt++) {
                uint32_t b0 = Vsu[(kk * 8 + tg) * VS_STRIDE + nt * 8 + g];
                uint32_t b1 = Vsu[(kk * 8 + tg + 4) * VS_STRIDE + nt * 8 + g];
                mma_tf32(o[nt], a0, a1, a2, a3, b0, b1);
            }
        }
    }

    if (half == 0) facs[wr + row_l] = l_run;
    __syncwarp();
    float il  = 1.0f / facs[wr + g];
    float il8 = 1.0f / facs[wr + g + 8];
    size_t r0 = ((size_t)(b * NN + brow + wr + g)) * DIMC + h * DD;
    size_t r8 = ((size_t)(b * NN + brow + wr + g + 8)) * DIMC + h * DD;
    #pragma unroll
    for (int nt = 0; nt < 8; nt++) {
        int col = nt * 8 + 2 * tg;
        *(float2*)&out[r0 + col] = make_float2(o[nt][0] * il,  o[nt][1] * il);
        *(float2*)&out[r8 + col] = make_float2(o[nt][2] * il8, o[nt][3] * il8);
    }
}

// ---------------- Launch ----------------
extern "C" void kernel_launch(void* const* d_in, const int* in_sizes, int n_in,
                              void* d_out, int out_size) {
    const float* x        = (const float*)d_in[0];
    const int*   mask     = (const int*)d_in[1];     // bool marshalled as int32
    const float* qkv_w    = (const float*)d_in[2];
    const float* CP_U_w   = (const float*)d_in[3];
    const float* CP_U_b   = (const float*)d_in[4];
    const float* CP_V_w   = (const float*)d_in[5];
    const float* CP_V_b   = (const float*)d_in[6];
    const float* CP_C     = (const float*)d_in[7];
    const float* CP_att   = (const float*)d_in[8];
    const float* proj_w   = (const float*)d_in[9];
    const float* proj_b   = (const float*)d_in[10];
    float* outp = (float*)d_out;

    float *p_qkv, *p_att, *p_WbigT, *p_WpT, *p_Wcq, *p_Wcp, *p_bqc, *p_bpc;
    cudaGetSymbolAddress((void**)&p_qkv,   g_qkv);
    cudaGetSymbolAddress((void**)&p_att,   g_att);
    cudaGetSymbolAddress((void**)&p_WbigT, g_WbigT);
    cudaGetSymbolAddress((void**)&p_WpT,   g_WpT);
    cudaGetSymbolAddress((void**)&p_Wcq,   g_Wcq);
    cudaGetSymbolAddress((void**)&p_Wcp,   g_Wcp);
    cudaGetSymbolAddress((void**)&p_bqc,   g_bqc);
    cudaGetSymbolAddress((void**)&p_bpc,   g_bpc);

    static bool attr_set = false;
    if (!attr_set) {
        cudaFuncSetAttribute(attn_mma_kernel,
                             cudaFuncAttributeMaxDynamicSharedMemorySize, ATT_SMEM_BYTES);
        cudaFuncSetAttribute(gemm_tf32<0>,
                             cudaFuncAttributeMaxDynamicSharedMemorySize, GEMM_SMEM_BYTES);
        cudaFuncSetAttribute(gemm_tf32<1>,
                             cudaFuncAttributeMaxDynamicSharedMemorySize, GEMM_SMEM_BYTES);
        attr_set = true;
    }

    cpc_kernel<<<16, 256>>>(CP_C, CP_att);
    wfac_kernel<<<512, 256>>>(CP_V_w);
    biascomb_kernel<<<256, 256>>>(CP_U_b, CP_V_b, proj_b);

    // Wcq[o][c] = qkv_w[o][c] + (WbigT @ CP_U_w)[o][c]   [1536,512], K=64
    gemm_tf32<0><<<dim3(2, 12), 256, GEMM_SMEM_BYTES>>>(p_WbigT, RR, CP_U_w, RR,
                                                        nullptr, qkv_w, p_Wcq, DIMC);
    // Wcp[o][c] = proj_w[o][c] + (WpT @ CP_U_w)[o][c]    [512,512],  K=64
    gemm_tf32<0><<<dim3(2, 4), 256, GEMM_SMEM_BYTES>>>(p_WpT, RR, CP_U_w, RR,
                                                       nullptr, proj_w, p_Wcp, DIMC);

    // qkv = x @ Wcq^T + bqc     [8192,1536], K=512, B in [N,K]
    gemm_tf32<1><<<dim3(6, MTOT / 128), 256, GEMM_SMEM_BYTES>>>(x, DIMC, p_Wcq, DIMC,
                                                                p_bqc, nullptr, p_qkv, 3 * DIMC);

    // tensor-core flash attention
    attn_mma_kernel<<<dim3(NN / 128, HH, BB), 256, ATT_SMEM_BYTES>>>(p_qkv, mask, p_att);

    // proj = att @ Wcp^T + bpc  [8192,512], K=512, B in [N,K]
    gemm_tf32<1><<<dim3(2, MTOT / 128), 256, GEMM_SMEM_BYTES>>>(p_att, DIMC, p_Wcp, DIMC,
                                                                p_bpc, nullptr, outp, DIMC);
}

// round 10
// speedup vs baseline: 1.1236x; 1.1236x over previous
#include <cuda_runtime.h>
#include <cstdint>
#include <cstddef>

// ---------------- Problem constants ----------------
#define BB   8
#define NN   1024
#define DIMC 512
#define HH   8
#define DD   64
#define RR   64          // R1 = R2 = R = 64
#define MTOT (BB*NN)     // 8192
#define SCALE_ATT 0.125f // D^-0.5
#define S_CONST 1.0f

// ---------------- Scratch (__device__ globals; no allocation allowed) ----------------
__device__ float g_qkv  [(size_t)MTOT*3*DIMC];
__device__ float g_att  [(size_t)MTOT*DIMC];
__device__ float g_CPc  [4*RR*RR];             // [f][ij]
__device__ float g_WT   [(3*DIMC+DIMC)*RR];    // rows 0..1535: WbigT, 1536..2047: WpT (xS)
__device__ float g_Wc   [(size_t)(3*DIMC+DIMC)*DIMC]; // rows 0..1535: Wcq, 1536..: Wcp
__device__ float g_bqc  [3*DIMC];              // CP_V_b(tiled) + CP_U_b@Wbig
__device__ float g_bpc  [DIMC];                // proj_b + S*CP_V_b + CP_U_b@Wp

// ---------------- Small precompute kernels ----------------
// CPc[f][ij] = sum_r CP_C[ij][r] * CP_att[r][f];  16 blocks x 256 thr
__global__ void cpc_kernel(const float* __restrict__ CP_C, const float* __restrict__ CP_att) {
    __shared__ float att_s[RR * 4];
    int tid = threadIdx.x;
    att_s[tid] = CP_att[tid];
    __syncthreads();
    int ij = blockIdx.x * 256 + tid;
    const float4* row = (const float4*)&CP_C[(size_t)ij << 6];
    float a0 = 0.f, a1 = 0.f, a2 = 0.f, a3 = 0.f;
    #pragma unroll
    for (int r4 = 0; r4 < 16; r4++) {
        float4 v = row[r4];
        const float* at = &att_s[r4 * 16];
        a0 += v.x * at[0]  + v.y * at[4]  + v.z * at[8]  + v.w * at[12];
        a1 += v.x * at[1]  + v.y * at[5]  + v.z * at[9]  + v.w * at[13];
        a2 += v.x * at[2]  + v.y * at[6]  + v.z * at[10] + v.w * at[14];
        a3 += v.x * at[3]  + v.y * at[7]  + v.z * at[11] + v.w * at[15];
    }
    g_CPc[0 * 4096 + ij] = a0;
    g_CPc[1 * 4096 + ij] = a1;
    g_CPc[2 * 4096 + ij] = a2;
    g_CPc[3 * 4096 + ij] = a3;
}

// g_WT[o][r] = sum_s CPc[f(o)][r*64+s] * CP_V_w[d(o)][s]  (xS for proj rows)
__global__ void wfac_kernel(const float* __restrict__ CP_V_w) {
    int idx = blockIdx.x * 256 + threadIdx.x;   // 131072
    int r = idx & 63;
    int o = idx >> 6;                           // 0..2047
    int f, d;
    if (o < 3 * DIMC) { f = o >> 9; d = o & 511; }
    else              { f = 3;      d = o - 3 * DIMC; }
    const float4* cp = (const float4*)&g_CPc[f * 4096 + r * RR];
    const float4* vw = (const float4*)&CP_V_w[(size_t)d * RR];
    float s = 0.f;
    #pragma unroll
    for (int i = 0; i < 16; i++) {
        float4 a = cp[i], b = vw[i];
        s += a.x * b.x + a.y * b.y + a.z * b.z + a.w * b.w;
    }
    g_WT[o * RR + r] = (o < 3 * DIMC) ? s : s * S_CONST;
}

// warp-per-output bias folds
__global__ void biascomb_kernel(const float* __restrict__ CP_U_b,
                                const float* __restrict__ CP_V_b,
                                const float* __restrict__ proj_b) {
    int w = blockIdx.x * 8 + (threadIdx.x >> 5);  // 0..2047
    int lane = threadIdx.x & 31;
    const float* row = &g_WT[w * RR];
    float s = CP_U_b[lane] * row[lane] + CP_U_b[lane + 32] * row[lane + 32];
    #pragma unroll
    for (int off = 16; off > 0; off >>= 1)
        s += __shfl_down_sync(0xffffffffu, s, off);
    if (lane == 0) {
        if (w < 3 * DIMC) g_bqc[w] = CP_V_b[w & 511] + s;
        else {
            int d = w - 3 * DIMC;
            g_bpc[d] = proj_b[d] + S_CONST * CP_V_b[d] + s;
        }
    }
}

// ---------------- tf32 helpers ----------------
__device__ __forceinline__ uint32_t f2tf(float x) {
    uint32_t r;
    asm("cvt.rna.tf32.f32 %0, %1;" : "=r"(r) : "f"(x));
    return r;
}

__device__ __forceinline__ void mma_tf32(float c[4], uint32_t a0, uint32_t a1,
                                         uint32_t a2, uint32_t a3,
                                         uint32_t b0, uint32_t b1) {
    asm volatile(
        "mma.sync.aligned.m16n8k8.row.col.f32.tf32.tf32.f32 "
        "{%0,%1,%2,%3}, {%4,%5,%6,%7}, {%8,%9}, {%0,%1,%2,%3};\n"
        : "+f"(c[0]), "+f"(c[1]), "+f"(c[2]), "+f"(c[3])
        : "r"(a0), "r"(a1), "r"(a2), "r"(a3), "r"(b0), "r"(b1));
}

// ---------------- Double-buffered tf32 GEMM (round-8 proven shape) ----------------
// C[M,N] = A[M,K]@B (+ bias[N]) (+ split Cadd)
// BNK=1: B stored [N,K] row-major. BNK=0: B stored [K,N] row-major.
// BM=BN=128, BK=16, 256 thr (8 warps: 2m x 4n), warp tile 64x32.
// __launch_bounds__(256,2): cap regs at 128 -> 2 CTAs/SM (static smem 40KB each).
template<int BNK>
__global__ __launch_bounds__(256, 2)
void gemm_tf32(const float* __restrict__ A, int lda,
               const float* __restrict__ B, int K,
               const float* __restrict__ bias,
               const float* __restrict__ Cadd, const float* __restrict__ Cadd2,
               int cadd_split,
               float* __restrict__ C, int N) {
    __shared__ uint32_t As[2][128][20];
    __shared__ uint32_t Bs[2][128][20];

    int tid  = threadIdx.x;
    int lane = tid & 31;
    int warp = tid >> 5;
    int warp_m = (warp >> 2) * 64;
    int warp_n = (warp & 3) * 32;
    int bm0 = blockIdx.y * 128;
    int bn0 = blockIdx.x * 128;
    int lr = lane >> 2;
    int lc = lane & 3;

    float acc[4][4][4];
    #pragma unroll
    for (int i = 0; i < 4; i++)
        #pragma unroll
        for (int j = 0; j < 4; j++)
            #pragma unroll
            for (int k = 0; k < 4; k++) acc[i][j][k] = 0.f;

    int a_m = tid >> 2;                // 0..63
    int a_k = (tid & 3) * 4;           // 0,4,8,12
    const float* pa0 = &A[(size_t)(bm0 + a_m) * lda + a_k];
    const float* pa1 = &A[(size_t)(bm0 + a_m + 64) * lda + a_k];

    int bkn_k = tid >> 4;              // KN: 0..15
    int bkn_n = (tid & 15) * 8;        // KN: 0..120
    int bnk_n = tid >> 1;              // NK: 0..127
    int bnk_k = (tid & 1) * 8;         // NK: 0 or 8
    const float* pb_kn = &B[(size_t)bkn_k * N + bn0 + bkn_n];
    const float* pb_nk = &B[(size_t)(bn0 + bnk_n) * K + bnk_k];

    float4 av0, av1, bv0, bv1;

    av0 = *(const float4*)pa0;
    av1 = *(const float4*)pa1;
    if (BNK) {
        bv0 = *(const float4*)pb_nk;
        bv1 = *(const float4*)(pb_nk + 4);
    } else {
        bv0 = *(const float4*)pb_kn;
        bv1 = *(const float4*)(pb_kn + 4);
    }
    {
        uint4 wa0 = make_uint4(f2tf(av0.x), f2tf(av0.y), f2tf(av0.z), f2tf(av0.w));
        uint4 wa1 = make_uint4(f2tf(av1.x), f2tf(av1.y), f2tf(av1.z), f2tf(av1.w));
        *(uint4*)&As[0][a_m][a_k]      = wa0;
        *(uint4*)&As[0][a_m + 64][a_k] = wa1;
        if (BNK) {
            uint4 wb0 = make_uint4(f2tf(bv0.x), f2tf(bv0.y), f2tf(bv0.z), f2tf(bv0.w));
            uint4 wb1 = make_uint4(f2tf(bv1.x), f2tf(bv1.y), f2tf(bv1.z), f2tf(bv1.w));
            *(uint4*)&Bs[0][bnk_n][bnk_k]     = wb0;
            *(uint4*)&Bs[0][bnk_n][bnk_k + 4] = wb1;
        } else {
            Bs[0][bkn_n + 0][bkn_k] = f2tf(bv0.x);
            Bs[0][bkn_n + 1][bkn_k] = f2tf(bv0.y);
            Bs[0][bkn_n + 2][bkn_k] = f2tf(bv0.z);
            Bs[0][bkn_n + 3][bkn_k] = f2tf(bv0.w);
            Bs[0][bkn_n + 4][bkn_k] = f2tf(bv1.x);
            Bs[0][bkn_n + 5][bkn_k] = f2tf(bv1.y);
            Bs[0][bkn_n + 6][bkn_k] = f2tf(bv1.z);
            Bs[0][bkn_n + 7][bkn_k] = f2tf(bv1.w);
        }
    }
    __syncthreads();

    int T = K / 16;
    #pragma unroll 1
    for (int t = 0; t < T; t++) {
        int p = t & 1;
        if (t + 1 < T) {
            int k0 = (t + 1) * 16;
            av0 = *(const float4*)(pa0 + k0);
            av1 = *(const float4*)(pa1 + k0);
            if (BNK) {
                bv0 = *(const float4*)(pb_nk + k0);
                bv1 = *(const float4*)(pb_nk + k0 + 4);
            } else {
                bv0 = *(const float4*)(pb_kn + (size_t)k0 * N);
                bv1 = *(const float4*)(pb_kn + (size_t)k0 * N + 4);
            }
        }

        #pragma unroll
        for (int kk = 0; kk < 16; kk += 8) {
            uint32_t af[4][4], bf[4][2];
            #pragma unroll
            for (int mt = 0; mt < 4; mt++) {
                int r = warp_m + mt * 16 + lr;
                af[mt][0] = As[p][r][kk + lc];
                af[mt][1] = As[p][r + 8][kk + lc];
                af[mt][2] = As[p][r][kk + 4 + lc];
                af[mt][3] = As[p][r + 8][kk + 4 + lc];
            }
            #pragma unroll
            for (int nt = 0; nt < 4; nt++) {
                int c = warp_n + nt * 8 + lr;
                bf[nt][0] = Bs[p][c][kk + lc];
                bf[nt][1] = Bs[p][c][kk + 4 + lc];
            }
            #pragma unroll
            for (int mt = 0; mt < 4; mt++)
                #pragma unroll
                for (int nt = 0; nt < 4; nt++)
                    mma_tf32(acc[mt][nt], af[mt][0], af[mt][1], af[mt][2], af[mt][3],
                             bf[nt][0], bf[nt][1]);
        }

        if (t + 1 < T) {
            int q = 1 - p;
            uint4 wa0 = make_uint4(f2tf(av0.x), f2tf(av0.y), f2tf(av0.z), f2tf(av0.w));
            uint4 wa1 = make_uint4(f2tf(av1.x), f2tf(av1.y), f2tf(av1.z), f2tf(av1.w));
            *(uint4*)&As[q][a_m][a_k]      = wa0;
            *(uint4*)&As[q][a_m + 64][a_k] = wa1;
            if (BNK) {
                uint4 wb0 = make_uint4(f2tf(bv0.x), f2tf(bv0.y), f2tf(bv0.z), f2tf(bv0.w));
                uint4 wb1 = make_uint4(f2tf(bv1.x), f2tf(bv1.y), f2tf(bv1.z), f2tf(bv1.w));
                *(uint4*)&Bs[q][bnk_n][bnk_k]     = wb0;
                *(uint4*)&Bs[q][bnk_n][bnk_k + 4] = wb1;
            } else {
                Bs[q][bkn_n + 0][bkn_k] = f2tf(bv0.x);
                Bs[q][bkn_n + 1][bkn_k] = f2tf(bv0.y);
                Bs[q][bkn_n + 2][bkn_k] = f2tf(bv0.z);
                Bs[q][bkn_n + 3][bkn_k] = f2tf(bv0.w);
                Bs[q][bkn_n + 4][bkn_k] = f2tf(bv1.x);
                Bs[q][bkn_n + 5][bkn_k] = f2tf(bv1.y);
                Bs[q][bkn_n + 6][bkn_k] = f2tf(bv1.z);
                Bs[q][bkn_n + 7][bkn_k] = f2tf(bv1.w);
            }
        }
        __syncthreads();
    }

    // Epilogue: optional bias + optional split matrix add + store
    #pragma unroll
    for (int mt = 0; mt < 4; mt++) {
        int row = bm0 + warp_m + mt * 16 + lr;
        #pragma unroll
        for (int nt = 0; nt < 4; nt++) {
            int col = bn0 + warp_n + nt * 8 + lc * 2;
            float b0 = 0.f, b1 = 0.f;
            if (bias) { b0 = bias[col]; b1 = bias[col + 1]; }
            float2 v0 = make_float2(acc[mt][nt][0] + b0, acc[mt][nt][1] + b1);
            float2 v1 = make_float2(acc[mt][nt][2] + b0, acc[mt][nt][3] + b1);
            if (Cadd) {
                const float* ca = (row < cadd_split) ? &Cadd[(size_t)row * N]
                                                     : &Cadd2[(size_t)(row - cadd_split) * N];
                // rows row and row+8 are on the same side (split % 128 == 0, tile spans 16)
                const float* ca8 = (row < cadd_split) ? &Cadd[(size_t)(row + 8) * N]
                                                      : &Cadd2[(size_t)(row + 8 - cadd_split) * N];
                float2 c0 = *(const float2*)&ca[col];
                float2 c1 = *(const float2*)&ca8[col];
                v0.x += c0.x; v0.y += c0.y;
                v1.x += c1.x; v1.y += c1.y;
            }
            *(float2*)&C[(size_t)row * N + col] = v0;
            *(float2*)&C[(size_t)(row + 8) * N + col] = v1;
        }
    }
}

// ---------------- Tensor-core flash attention (tf32 mma, fp32 softmax) ----------------
#define SP_STRIDE 68
#define KS_STRIDE 68
#define VS_STRIDE 72
#define ATT_SP_OFF   0
#define ATT_KS_OFF   (128*SP_STRIDE)
#define ATT_VS_OFF   (ATT_KS_OFF + 64*KS_STRIDE)
#define ATT_MA_OFF   (ATT_VS_OFF + 64*VS_STRIDE)
#define ATT_FAC_OFF  (ATT_MA_OFF + 64)
#define ATT_SMEM_FLOATS (ATT_FAC_OFF + 128)
#define ATT_SMEM_BYTES  (ATT_SMEM_FLOATS * 4)

extern __shared__ float att_sm[];

__global__ __launch_bounds__(256, 2)
void attn_mma_kernel(const float* __restrict__ qkv, const int* __restrict__ mask,
                     float* __restrict__ out) {
    float*    SP   = att_sm + ATT_SP_OFF;
    float*    Ks   = att_sm + ATT_KS_OFF;
    float*    Vs   = att_sm + ATT_VS_OFF;
    float*    ma   = att_sm + ATT_MA_OFF;
    float*    facs = att_sm + ATT_FAC_OFF;
    uint32_t* SPu  = (uint32_t*)SP;
    uint32_t* Ksu  = (uint32_t*)Ks;
    uint32_t* Vsu  = (uint32_t*)Vs;

    int tid = threadIdx.x, lane = tid & 31, warp = tid >> 5;
    int b = blockIdx.z, h = blockIdx.y;
    int brow = blockIdx.x * 128;
    int g = lane >> 2, tg = lane & 3;
    int wr = warp * 16;
    int row_l = lane >> 1, half = lane & 1;

    {
        int row = tid >> 1, hf = tid & 1;
        const float* qp = qkv + ((size_t)(b * NN + brow + row)) * (3 * DIMC) + h * DD + hf * 32;
        uint32_t* dst = SPu + row * SP_STRIDE + hf * 32;
        #pragma unroll
        for (int i = 0; i < 8; i++) {
            float4 v = *(const float4*)(qp + i * 4);
            dst[i * 4 + 0] = f2tf(v.x * SCALE_ATT);
            dst[i * 4 + 1] = f2tf(v.y * SCALE_ATT);
            dst[i * 4 + 2] = f2tf(v.z * SCALE_ATT);
            dst[i * 4 + 3] = f2tf(v.w * SCALE_ATT);
        }
    }
    __syncthreads();

    uint32_t aq[8][4];
    #pragma unroll
    for (int kk = 0; kk < 8; kk++) {
        aq[kk][0] = SPu[(wr + g) * SP_STRIDE + kk * 8 + tg];
        aq[kk][1] = SPu[(wr + g + 8) * SP_STRIDE + kk * 8 + tg];
        aq[kk][2] = SPu[(wr + g) * SP_STRIDE + kk * 8 + 4 + tg];
        aq[kk][3] = SPu[(wr + g + 8) * SP_STRIDE + kk * 8 + 4 + tg];
    }

    float o[8][4];
    #pragma unroll
    for (int nt = 0; nt < 8; nt++)
        #pragma unroll
        for (int i = 0; i < 4; i++) o[nt][i] = 0.f;
    float m_run = -1e30f, l_run = 0.f;

    #pragma unroll 1
    for (int t = 0; t < NN / 64; t++) {
        int k0 = t * 64;
        __syncthreads();
        {
            int r = tid >> 2, c4 = (tid & 3) * 16;
            size_t base = ((size_t)(b * NN + k0 + r)) * (3 * DIMC) + h * DD + c4;
            const float* kp = qkv + base + DIMC;
            const float* vp = qkv + base + 2 * DIMC;
            uint32_t* kd = Ksu + r * KS_STRIDE + c4;
            uint32_t* vd = Vsu + r * VS_STRIDE + c4;
            #pragma unroll
            for (int i = 0; i < 4; i++) {
                float4 kv = *(const float4*)(kp + i * 4);
                float4 vv = *(const float4*)(vp + i * 4);
                kd[i * 4 + 0] = f2tf(kv.x);
                kd[i * 4 + 1] = f2tf(kv.y);
                kd[i * 4 + 2] = f2tf(kv.z);
                kd[i * 4 + 3] = f2tf(kv.w);
                vd[i * 4 + 0] = f2tf(vv.x);
                vd[i * 4 + 1] = f2tf(vv.y);
                vd[i * 4 + 2] = f2tf(vv.z);
                vd[i * 4 + 3] = f2tf(vv.w);
            }
            if (tid < 64) ma[tid] = mask[b * NN + k0 + tid] ? 0.f : -1e30f;
        }
        __syncthreads();

        float s[8][4];
        #pragma unroll
        for (int nt = 0; nt < 8; nt++)
            #pragma unroll
            for (int i = 0; i < 4; i++) s[nt][i] = 0.f;
        #pragma unroll
        for (int kk = 0; kk < 8; kk++) {
            #pragma unroll
            for (int nt = 0; nt < 8; nt++) {
                uint32_t b0 = Ksu[(nt * 8 + g) * KS_STRIDE + kk * 8 + tg];
                uint32_t b1 = Ksu[(nt * 8 + g) * KS_STRIDE + kk * 8 + 4 + tg];
                mma_tf32(s[nt], aq[kk][0], aq[kk][1], aq[kk][2], aq[kk][3], b0, b1);
            }
        }
        #pragma unroll
        for (int nt = 0; nt < 8; nt++) {
            *(float2*)&SP[(wr + g) * SP_STRIDE + nt * 8 + 2 * tg]     = make_float2(s[nt][0], s[nt][1]);
            *(float2*)&SP[(wr + g + 8) * SP_STRIDE + nt * 8 + 2 * tg] = make_float2(s[nt][2], s[nt][3]);
        }
        __syncwarp();

        {
            float* srow = SP + (wr + row_l) * SP_STRIDE + half * 32;
            const float* mrow = ma + half * 32;
            float tm = -1e30f;
            #pragma unroll
            for (int j = 0; j < 32; j++) tm = fmaxf(tm, srow[j] + mrow[j]);
            tm = fmaxf(tm, __shfl_xor_sync(0xffffffffu, tm, 1));
            float m_new = fmaxf(m_run, tm);
            float fac = __expf(m_run - m_new);
            float ps = 0.f;
            uint32_t* prow = SPu + (wr + row_l) * SP_STRIDE + half * 32;
            #pragma unroll
            for (int j = 0; j < 32; j++) {
                float p = __expf(srow[j] + mrow[j] - m_new);
                ps += p;
                prow[j] = f2tf(p);
            }
            ps += __shfl_xor_sync(0xffffffffu, ps, 1);
            l_run = l_run * fac + ps;
            m_run = m_new;
            if (half == 0) facs[wr + row_l] = fac;
        }
        __syncwarp();

        float fg  = facs[wr + g];
        float fg8 = facs[wr + g + 8];
        #pragma unroll
        for (int nt = 0; nt < 8; nt++) {
            o[nt][0] *= fg;  o[nt][1] *= fg;
            o[nt][2] *= fg8; o[nt][3] *= fg8;
        }
        #pragma unroll
        for (int kk = 0; kk < 8; kk++) {
            uint32_t a0 = SPu[(wr + g) * SP_STRIDE + kk * 8 + tg];
            uint32_t a1 = SPu[(wr + g + 8) * SP_STRIDE + kk * 8 + tg];
            uint32_t a2 = SPu[(wr + g) * SP_STRIDE + kk * 8 + 4 + tg];
            uint32_t a3 = SPu[(wr + g + 8) * SP_STRIDE + kk * 8 + 4 + tg];
            #pragma unroll
            for (int nt = 0; nt < 8; nt++) {
                uint32_t b0 = Vsu[(kk * 8 + tg) * VS_STRIDE + nt * 8 + g];
                uint32_t b1 = Vsu[(kk * 8 + tg + 4) * VS_STRIDE + nt * 8 + g];
                mma_tf32(o[nt], a0, a1, a2, a3, b0, b1);
            }
        }
    }

    if (half == 0) facs[wr + row_l] = l_run;
    __syncwarp();
    float il  = 1.0f / facs[wr + g];
    float il8 = 1.0f / facs[wr + g + 8];
    size_t r0 = ((size_t)(b * NN + brow + wr + g)) * DIMC + h * DD;
    size_t r8 = ((size_t)(b * NN + brow + wr + g + 8)) * DIMC + h * DD;
    #pragma unroll
    for (int nt = 0; nt < 8; nt++) {
        int col = nt * 8 + 2 * tg;
        *(float2*)&out[r0 + col] = make_float2(o[nt][0] * il,  o[nt][1] * il);
        *(float2*)&out[r8 + col] = make_float2(o[nt][2] * il8, o[nt][3] * il8);
    }
}

// ---------------- Launch ----------------
extern "C" void kernel_launch(void* const* d_in, const int* in_sizes, int n_in,
                              void* d_out, int out_size) {
    const float* x        = (const float*)d_in[0];
    const int*   mask     = (const int*)d_in[1];     // bool marshalled as int32
    const float* qkv_w    = (const float*)d_in[2];
    const float* CP_U_w   = (const float*)d_in[3];
    const float* CP_U_b   = (const float*)d_in[4];
    const float* CP_V_w   = (const float*)d_in[5];
    const float* CP_V_b   = (const float*)d_in[6];
    const float* CP_C     = (const float*)d_in[7];
    const float* CP_att   = (const float*)d_in[8];
    const float* proj_w   = (const float*)d_in[9];
    const float* proj_b   = (const float*)d_in[10];
    float* outp = (float*)d_out;

    float *p_qkv, *p_att, *p_WT, *p_Wc, *p_bqc, *p_bpc;
    cudaGetSymbolAddress((void**)&p_qkv, g_qkv);
    cudaGetSymbolAddress((void**)&p_att, g_att);
    cudaGetSymbolAddress((void**)&p_WT,  g_WT);
    cudaGetSymbolAddress((void**)&p_Wc,  g_Wc);
    cudaGetSymbolAddress((void**)&p_bqc, g_bqc);
    cudaGetSymbolAddress((void**)&p_bpc, g_bpc);

    static bool attr_set = false;
    if (!attr_set) {
        cudaFuncSetAttribute(attn_mma_kernel,
                             cudaFuncAttributeMaxDynamicSharedMemorySize, ATT_SMEM_BYTES);
        attr_set = true;
    }

    cpc_kernel<<<16, 256>>>(CP_C, CP_att);
    wfac_kernel<<<512, 256>>>(CP_V_w);
    biascomb_kernel<<<256, 256>>>(CP_U_b, CP_V_b, proj_b);

    // Fused combine: g_Wc[0..2047][512] = g_WT@CP_U_w + [qkv_w; proj_w]   K=64
    gemm_tf32<0><<<dim3(4, 16), 256>>>(p_WT, RR, CP_U_w, RR,
                                       nullptr, qkv_w, proj_w, 3 * DIMC,
                                       p_Wc, DIMC);

    // qkv = x @ Wcq^T + bqc     [8192,1536], K=512, B rows 0..1535 of g_Wc ([N,K])
    gemm_tf32<1><<<dim3(12, MTOT / 128), 256>>>(x, DIMC, p_Wc, DIMC,
                                                p_bqc, nullptr, nullptr, 0,
                                                p_qkv, 3 * DIMC);

    // tensor-core flash attention
    attn_mma_kernel<<<dim3(NN / 128, HH, BB), 256, ATT_SMEM_BYTES>>>(p_qkv, mask, p_att);

    // proj = att @ Wcp^T + bpc  [8192,512], K=512, B rows 1536..2047 of g_Wc
    gemm_tf32<1><<<dim3(4, MTOT / 128), 256>>>(p_att, DIMC, p_Wc + (size_t)3 * DIMC * DIMC, DIMC,
                                               p_bpc, nullptr, nullptr, 0,
                                               outp, DIMC);
}

// round 11
// speedup vs baseline: 1.1863x; 1.0557x over previous
#include <cuda_runtime.h>
#include <cstdint>
#include <cstddef>

// ---------------- Problem constants ----------------
#define BB   8
#define NN   1024
#define DIMC 512
#define HH   8
#define DD   64
#define RR   64          // R1 = R2 = R = 64
#define MTOT (BB*NN)     // 8192
#define SCALE_ATT 0.125f // D^-0.5
#define S_CONST 1.0f

// ---------------- Scratch (__device__ globals; no allocation allowed) ----------------
__device__ float g_qkv  [(size_t)MTOT*3*DIMC];
__device__ float g_att  [(size_t)MTOT*DIMC];
__device__ float g_CPc  [4*RR*RR];             // [f][ij]
__device__ float g_WT   [(3*DIMC+DIMC)*RR];    // rows 0..1535: WbigT, 1536..2047: WpT (xS)
__device__ float g_Wc   [(size_t)(3*DIMC+DIMC)*DIMC]; // rows 0..1535: Wcq, 1536..: Wcp
__device__ float g_bqc  [3*DIMC];              // CP_V_b(tiled) + CP_U_b@Wbig
__device__ float g_bpc  [DIMC];                // proj_b + S*CP_V_b + CP_U_b@Wp

// ---------------- Small precompute kernels ----------------
__global__ void cpc_kernel(const float* __restrict__ CP_C, const float* __restrict__ CP_att) {
    __shared__ float att_s[RR * 4];
    int tid = threadIdx.x;
    att_s[tid] = CP_att[tid];
    __syncthreads();
    int ij = blockIdx.x * 256 + tid;
    const float4* row = (const float4*)&CP_C[(size_t)ij << 6];
    float a0 = 0.f, a1 = 0.f, a2 = 0.f, a3 = 0.f;
    #pragma unroll
    for (int r4 = 0; r4 < 16; r4++) {
        float4 v = row[r4];
        const float* at = &att_s[r4 * 16];
        a0 += v.x * at[0]  + v.y * at[4]  + v.z * at[8]  + v.w * at[12];
        a1 += v.x * at[1]  + v.y * at[5]  + v.z * at[9]  + v.w * at[13];
        a2 += v.x * at[2]  + v.y * at[6]  + v.z * at[10] + v.w * at[14];
        a3 += v.x * at[3]  + v.y * at[7]  + v.z * at[11] + v.w * at[15];
    }
    g_CPc[0 * 4096 + ij] = a0;
    g_CPc[1 * 4096 + ij] = a1;
    g_CPc[2 * 4096 + ij] = a2;
    g_CPc[3 * 4096 + ij] = a3;
}

__global__ void wfac_kernel(const float* __restrict__ CP_V_w) {
    int idx = blockIdx.x * 256 + threadIdx.x;   // 131072
    int r = idx & 63;
    int o = idx >> 6;                           // 0..2047
    int f, d;
    if (o < 3 * DIMC) { f = o >> 9; d = o & 511; }
    else              { f = 3;      d = o - 3 * DIMC; }
    const float4* cp = (const float4*)&g_CPc[f * 4096 + r * RR];
    const float4* vw = (const float4*)&CP_V_w[(size_t)d * RR];
    float s = 0.f;
    #pragma unroll
    for (int i = 0; i < 16; i++) {
        float4 a = cp[i], b = vw[i];
        s += a.x * b.x + a.y * b.y + a.z * b.z + a.w * b.w;
    }
    g_WT[o * RR + r] = (o < 3 * DIMC) ? s : s * S_CONST;
}

__global__ void biascomb_kernel(const float* __restrict__ CP_U_b,
                                const float* __restrict__ CP_V_b,
                                const float* __restrict__ proj_b) {
    int w = blockIdx.x * 8 + (threadIdx.x >> 5);  // 0..2047
    int lane = threadIdx.x & 31;
    const float* row = &g_WT[w * RR];
    float s = CP_U_b[lane] * row[lane] + CP_U_b[lane + 32] * row[lane + 32];
    #pragma unroll
    for (int off = 16; off > 0; off >>= 1)
        s += __shfl_down_sync(0xffffffffu, s, off);
    if (lane == 0) {
        if (w < 3 * DIMC) g_bqc[w] = CP_V_b[w & 511] + s;
        else {
            int d = w - 3 * DIMC;
            g_bpc[d] = proj_b[d] + S_CONST * CP_V_b[d] + s;
        }
    }
}

// ---------------- tf32 helpers ----------------
__device__ __forceinline__ uint32_t f2tf(float x) {
    uint32_t r;
    asm("cvt.rna.tf32.f32 %0, %1;" : "=r"(r) : "f"(x));
    return r;
}

__device__ __forceinline__ void mma_tf32(float c[4], uint32_t a0, uint32_t a1,
                                         uint32_t a2, uint32_t a3,
                                         uint32_t b0, uint32_t b1) {
    asm volatile(
        "mma.sync.aligned.m16n8k8.row.col.f32.tf32.tf32.f32 "
        "{%0,%1,%2,%3}, {%4,%5,%6,%7}, {%8,%9}, {%0,%1,%2,%3};\n"
        : "+f"(c[0]), "+f"(c[1]), "+f"(c[2]), "+f"(c[3])
        : "r"(a0), "r"(a1), "r"(a2), "r"(a3), "r"(b0), "r"(b1));
}

__device__ __forceinline__ void cp_async16(uint32_t smem_addr, const void* gptr) {
    asm volatile("cp.async.ca.shared.global [%0], [%1], 16;\n"
                 :: "r"(smem_addr), "l"(gptr));
}
__device__ __forceinline__ uint32_t smem_u32(const void* p) {
    return (uint32_t)__cvta_generic_to_shared(p);
}

// Shared dynamic-smem symbol
extern __shared__ float dyn_sm[];

// ---------------- cp.async 3-stage tf32 GEMM (B in [N,K], raw-fp32-as-tf32) ----------------
// C[M,N] = A[M,K]@B^T + bias[N].  BM=BN=128, BK=16, 256 thr, warp tile 64x32.
// Dynamic smem: As[3][128][20] + Bs[3][128][20] floats = 61440 bytes.
#define GST 20
#define GEMM_NK_SMEM ((3*128*GST*2) * 4)
#define ASM(s, r, c) As[((s) * 128 + (r)) * GST + (c)]
#define BSM(s, n, c) Bs[((s) * 128 + (n)) * GST + (c)]

__global__ __launch_bounds__(256, 2)
void gemm_nk_async(const float* __restrict__ A, int lda,
                   const float* __restrict__ B, int K,
                   const float* __restrict__ bias,
                   float* __restrict__ C, int N) {
    float* As = dyn_sm;
    float* Bs = dyn_sm + 3 * 128 * GST;

    int tid  = threadIdx.x;
    int lane = tid & 31;
    int warp = tid >> 5;
    int warp_m = (warp >> 2) * 64;
    int warp_n = (warp & 3) * 32;
    int bm0 = blockIdx.y * 128;
    int bn0 = blockIdx.x * 128;
    int lr = lane >> 2;
    int lc = lane & 3;

    float acc[4][4][4];
    #pragma unroll
    for (int i = 0; i < 4; i++)
        #pragma unroll
        for (int j = 0; j < 4; j++)
            #pragma unroll
            for (int k = 0; k < 4; k++) acc[i][j][k] = 0.f;

    // A loader: rows a_m, a_m+64; 16B chunk at a_k
    int a_m = tid >> 2;                // 0..63
    int a_k = (tid & 3) * 4;           // 0,4,8,12
    const float* pa0 = &A[(size_t)(bm0 + a_m) * lda + a_k];
    const float* pa1 = &A[(size_t)(bm0 + a_m + 64) * lda + a_k];
    uint32_t sa0 = smem_u32(&ASM(0, a_m, a_k));
    uint32_t sa1 = smem_u32(&ASM(0, a_m + 64, a_k));

    // B loader ([N,K]): row b_n, 8 floats at b_k (2 chunks)
    int b_n = tid >> 1;                // 0..127
    int b_k = (tid & 1) * 8;           // 0 or 8
    const float* pb = &B[(size_t)(bn0 + b_n) * K + b_k];
    uint32_t sb0 = smem_u32(&BSM(0, b_n, b_k));

    const uint32_t stage_bytes = 128 * GST * 4;

    // ---- prologue: issue stages 0 and 1 ----
    #pragma unroll
    for (int s = 0; s < 2; s++) {
        int k0 = s * 16;
        cp_async16(sa0 + s * stage_bytes, pa0 + k0);
        cp_async16(sa1 + s * stage_bytes, pa1 + k0);
        cp_async16(sb0 + s * stage_bytes, pb + k0);
        cp_async16(sb0 + s * stage_bytes + 16, pb + k0 + 4);
        asm volatile("cp.async.commit_group;\n" ::);
    }

    int T = K / 16;
    uint32_t* Asu = (uint32_t*)As;
    uint32_t* Bsu = (uint32_t*)Bs;

    #pragma unroll 1
    for (int t = 0; t < T; t++) {
        int p = t % 3;
        asm volatile("cp.async.wait_group 1;\n" ::);
        __syncthreads();

        // issue stage t+2
        int tn = t + 2;
        if (tn < T) {
            int s = tn % 3;
            int k0 = tn * 16;
            cp_async16(sa0 + s * stage_bytes, pa0 + k0);
            cp_async16(sa1 + s * stage_bytes, pa1 + k0);
            cp_async16(sb0 + s * stage_bytes, pb + k0);
            cp_async16(sb0 + s * stage_bytes + 16, pb + k0 + 4);
        }
        asm volatile("cp.async.commit_group;\n" ::);

        // ---- mma on stage p ----
        int pbase = p * 128 * GST;
        #pragma unroll
        for (int kk = 0; kk < 16; kk += 8) {
            uint32_t af[4][4], bf[4][2];
            #pragma unroll
            for (int mt = 0; mt < 4; mt++) {
                int r = warp_m + mt * 16 + lr;
                af[mt][0] = Asu[pbase + r * GST + kk + lc];
                af[mt][1] = Asu[pbase + (r + 8) * GST + kk + lc];
                af[mt][2] = Asu[pbase + r * GST + kk + 4 + lc];
                af[mt][3] = Asu[pbase + (r + 8) * GST + kk + 4 + lc];
            }
            #pragma unroll
            for (int nt = 0; nt < 4; nt++) {
                int c = warp_n + nt * 8 + lr;
                bf[nt][0] = Bsu[pbase + c * GST + kk + lc];
                bf[nt][1] = Bsu[pbase + c * GST + kk + 4 + lc];
            }
            #pragma unroll
            for (int mt = 0; mt < 4; mt++)
                #pragma unroll
                for (int nt = 0; nt < 4; nt++)
                    mma_tf32(acc[mt][nt], af[mt][0], af[mt][1], af[mt][2], af[mt][3],
                             bf[nt][0], bf[nt][1]);
        }
    }

    // Epilogue: bias + store
    #pragma unroll
    for (int mt = 0; mt < 4; mt++) {
        int row = bm0 + warp_m + mt * 16 + lr;
        #pragma unroll
        for (int nt = 0; nt < 4; nt++) {
            int col = bn0 + warp_n + nt * 8 + lc * 2;
            float b0 = bias[col], b1 = bias[col + 1];
            *(float2*)&C[(size_t)row * N + col] =
                make_float2(acc[mt][nt][0] + b0, acc[mt][nt][1] + b1);
            *(float2*)&C[(size_t)(row + 8) * N + col] =
                make_float2(acc[mt][nt][2] + b0, acc[mt][nt][3] + b1);
        }
    }
}

// ---------------- Combine GEMM (round-10 proven, B in [K,N], split Cadd) ----------------
__global__ __launch_bounds__(256, 2)
void gemm_kn(const float* __restrict__ A, int lda,
             const float* __restrict__ B, int K,
             const float* __restrict__ Cadd, const float* __restrict__ Cadd2,
             int cadd_split,
             float* __restrict__ C, int N) {
    __shared__ uint32_t As[2][128][20];
    __shared__ uint32_t Bs[2][128][20];

    int tid  = threadIdx.x;
    int lane = tid & 31;
    int warp = tid >> 5;
    int warp_m = (warp >> 2) * 64;
    int warp_n = (warp & 3) * 32;
    int bm0 = blockIdx.y * 128;
    int bn0 = blockIdx.x * 128;
    int lr = lane >> 2;
    int lc = lane & 3;

    float acc[4][4][4];
    #pragma unroll
    for (int i = 0; i < 4; i++)
        #pragma unroll
        for (int j = 0; j < 4; j++)
            #pragma unroll
            for (int k = 0; k < 4; k++) acc[i][j][k] = 0.f;

    int a_m = tid >> 2;
    int a_k = (tid & 3) * 4;
    const float* pa0 = &A[(size_t)(bm0 + a_m) * lda + a_k];
    const float* pa1 = &A[(size_t)(bm0 + a_m + 64) * lda + a_k];

    int bkn_k = tid >> 4;
    int bkn_n = (tid & 15) * 8;
    const float* pb_kn = &B[(size_t)bkn_k * N + bn0 + bkn_n];

    float4 av0, av1, bv0, bv1;
    av0 = *(const float4*)pa0;
    av1 = *(const float4*)pa1;
    bv0 = *(const float4*)pb_kn;
    bv1 = *(const float4*)(pb_kn + 4);
    {
        *(uint4*)&As[0][a_m][a_k]      = make_uint4(f2tf(av0.x), f2tf(av0.y), f2tf(av0.z), f2tf(av0.w));
        *(uint4*)&As[0][a_m + 64][a_k] = make_uint4(f2tf(av1.x), f2tf(av1.y), f2tf(av1.z), f2tf(av1.w));
        Bs[0][bkn_n + 0][bkn_k] = f2tf(bv0.x);
        Bs[0][bkn_n + 1][bkn_k] = f2tf(bv0.y);
        Bs[0][bkn_n + 2][bkn_k] = f2tf(bv0.z);
        Bs[0][bkn_n + 3][bkn_k] = f2tf(bv0.w);
        Bs[0][bkn_n + 4][bkn_k] = f2tf(bv1.x);
        Bs[0][bkn_n + 5][bkn_k] = f2tf(bv1.y);
        Bs[0][bkn_n + 6][bkn_k] = f2tf(bv1.z);
        Bs[0][bkn_n + 7][bkn_k] = f2tf(bv1.w);
    }
    __syncthreads();

    int T = K / 16;
    #pragma unroll 1
    for (int t = 0; t < T; t++) {
        int p = t & 1;
        if (t + 1 < T) {
            int k0 = (t + 1) * 16;
            av0 = *(const float4*)(pa0 + k0);
            av1 = *(const float4*)(pa1 + k0);
            bv0 = *(const float4*)(pb_kn + (size_t)k0 * N);
            bv1 = *(const float4*)(pb_kn + (size_t)k0 * N + 4);
        }

        #pragma unroll
        for (int kk = 0; kk < 16; kk += 8) {
            uint32_t af[4][4], bf[4][2];
            #pragma unroll
            for (int mt = 0; mt < 4; mt++) {
                int r = warp_m + mt * 16 + lr;
                af[mt][0] = As[p][r][kk + lc];
                af[mt][1] = As[p][r + 8][kk + lc];
                af[mt][2] = As[p][r][kk + 4 + lc];
                af[mt][3] = As[p][r + 8][kk + 4 + lc];
            }
            #pragma unroll
            for (int nt = 0; nt < 4; nt++) {
                int c = warp_n + nt * 8 + lr;
                bf[nt][0] = Bs[p][c][kk + lc];
                bf[nt][1] = Bs[p][c][kk + 4 + lc];
            }
            #pragma unroll
            for (int mt = 0; mt < 4; mt++)
                #pragma unroll
                for (int nt = 0; nt < 4; nt++)
                    mma_tf32(acc[mt][nt], af[mt][0], af[mt][1], af[mt][2], af[mt][3],
                             bf[nt][0], bf[nt][1]);
        }

        if (t + 1 < T) {
            int q = 1 - p;
            *(uint4*)&As[q][a_m][a_k]      = make_uint4(f2tf(av0.x), f2tf(av0.y), f2tf(av0.z), f2tf(av0.w));
            *(uint4*)&As[q][a_m + 64][a_k] = make_uint4(f2tf(av1.x), f2tf(av1.y), f2tf(av1.z), f2tf(av1.w));
            Bs[q][bkn_n + 0][bkn_k] = f2tf(bv0.x);
            Bs[q][bkn_n + 1][bkn_k] = f2tf(bv0.y);
            Bs[q][bkn_n + 2][bkn_k] = f2tf(bv0.z);
            Bs[q][bkn_n + 3][bkn_k] = f2tf(bv0.w);
            Bs[q][bkn_n + 4][bkn_k] = f2tf(bv1.x);
            Bs[q][bkn_n + 5][bkn_k] = f2tf(bv1.y);
            Bs[q][bkn_n + 6][bkn_k] = f2tf(bv1.z);
            Bs[q][bkn_n + 7][bkn_k] = f2tf(bv1.w);
        }
        __syncthreads();
    }

    #pragma unroll
    for (int mt = 0; mt < 4; mt++) {
        int row = bm0 + warp_m + mt * 16 + lr;
        #pragma unroll
        for (int nt = 0; nt < 4; nt++) {
            int col = bn0 + warp_n + nt * 8 + lc * 2;
            float2 v0 = make_float2(acc[mt][nt][0], acc[mt][nt][1]);
            float2 v1 = make_float2(acc[mt][nt][2], acc[mt][nt][3]);
            const float* ca  = (row < cadd_split) ? &Cadd[(size_t)row * N]
                                                  : &Cadd2[(size_t)(row - cadd_split) * N];
            const float* ca8 = (row < cadd_split) ? &Cadd[(size_t)(row + 8) * N]
                                                  : &Cadd2[(size_t)(row + 8 - cadd_split) * N];
            float2 c0 = *(const float2*)&ca[col];
            float2 c1 = *(const float2*)&ca8[col];
            v0.x += c0.x; v0.y += c0.y;
            v1.x += c1.x; v1.y += c1.y;
            *(float2*)&C[(size_t)row * N + col] = v0;
            *(float2*)&C[(size_t)(row + 8) * N + col] = v1;
        }
    }
}

// ---------------- Tensor-core flash attention (raw-fp32 tf32 mma, fp32 softmax) ----------------
#define SP_STRIDE 68
#define KS_STRIDE 68
#define VS_STRIDE 72
#define ATT_SP_OFF   0
#define ATT_KS_OFF   (128*SP_STRIDE)
#define ATT_VS_OFF   (ATT_KS_OFF + 64*KS_STRIDE)
#define ATT_MA_OFF   (ATT_VS_OFF + 64*VS_STRIDE)
#define ATT_FAC_OFF  (ATT_MA_OFF + 64)
#define ATT_SMEM_FLOATS (ATT_FAC_OFF + 128)
#define ATT_SMEM_BYTES  (ATT_SMEM_FLOATS * 4)

__global__ __launch_bounds__(256, 2)
void attn_mma_kernel(const float* __restrict__ qkv, const int* __restrict__ mask,
                     float* __restrict__ out) {
    float*    SP   = dyn_sm + ATT_SP_OFF;
    float*    Ks   = dyn_sm + ATT_KS_OFF;
    float*    Vs   = dyn_sm + ATT_VS_OFF;
    float*    ma   = dyn_sm + ATT_MA_OFF;
    float*    facs = dyn_sm + ATT_FAC_OFF;
    uint32_t* SPu  = (uint32_t*)SP;
    uint32_t* Ksu  = (uint32_t*)Ks;
    uint32_t* Vsu  = (uint32_t*)Vs;

    int tid = threadIdx.x, lane = tid & 31, warp = tid >> 5;
    int b = blockIdx.z, h = blockIdx.y;
    int brow = blockIdx.x * 128;
    int g = lane >> 2, tg = lane & 3;
    int wr = warp * 16;
    int row_l = lane >> 1, half = lane & 1;

    // --- stage Q (raw bits) into SP via cp.async ---
    {
        int row = tid >> 1, hf = tid & 1;
        const float* qp = qkv + ((size_t)(b * NN + brow + row)) * (3 * DIMC) + h * DD + hf * 32;
        uint32_t dst = smem_u32(&SP[row * SP_STRIDE + hf * 32]);
        #pragma unroll
        for (int i = 0; i < 8; i++)
            cp_async16(dst + i * 16, qp + i * 4);
        asm volatile("cp.async.commit_group;\n" ::);
        asm volatile("cp.async.wait_group 0;\n" ::);
    }
    __syncthreads();

    // Q fragments (raw fp32 bits, SCALE applied post-mma in softmax)
    uint32_t aq[8][4];
    #pragma unroll
    for (int kk = 0; kk < 8; kk++) {
        aq[kk][0] = SPu[(wr + g) * SP_STRIDE + kk * 8 + tg];
        aq[kk][1] = SPu[(wr + g + 8) * SP_STRIDE + kk * 8 + tg];
        aq[kk][2] = SPu[(wr + g) * SP_STRIDE + kk * 8 + 4 + tg];
        aq[kk][3] = SPu[(wr + g + 8) * SP_STRIDE + kk * 8 + 4 + tg];
    }

    float o[8][4];
    #pragma unroll
    for (int nt = 0; nt < 8; nt++)
        #pragma unroll
        for (int i = 0; i < 4; i++) o[nt][i] = 0.f;
    float m_run = -1e30f, l_run = 0.f;

    #pragma unroll 1
    for (int t = 0; t < NN / 64; t++) {
        int k0 = t * 64;
        __syncthreads();   // all warps done with prev Ks/Vs
        {
            int r = tid >> 2, c4 = (tid & 3) * 16;
            size_t base = ((size_t)(b * NN + k0 + r)) * (3 * DIMC) + h * DD + c4;
            const float* kp = qkv + base + DIMC;
            const float* vp = qkv + base + 2 * DIMC;
            uint32_t kd = smem_u32(&Ks[r * KS_STRIDE + c4]);
            uint32_t vd = smem_u32(&Vs[r * VS_STRIDE + c4]);
            #pragma unroll
            for (int i = 0; i < 4; i++) {
                cp_async16(kd + i * 16, kp + i * 4);
                cp_async16(vd + i * 16, vp + i * 4);
            }
            asm volatile("cp.async.commit_group;\n" ::);
            if (tid < 64) ma[tid] = mask[b * NN + k0 + tid] ? 0.f : -1e30f;
            asm volatile("cp.async.wait_group 0;\n" ::);
        }
        __syncthreads();

        // QK^T (unscaled)
        float s[8][4];
        #pragma unroll
        for (int nt = 0; nt < 8; nt++)
            #pragma unroll
            for (int i = 0; i < 4; i++) s[nt][i] = 0.f;
        #pragma unroll
        for (int kk = 0; kk < 8; kk++) {
            #pragma unroll
            for (int nt = 0; nt < 8; nt++) {
                uint32_t b0 = Ksu[(nt * 8 + g) * KS_STRIDE + kk * 8 + tg];
                uint32_t b1 = Ksu[(nt * 8 + g) * KS_STRIDE + kk * 8 + 4 + tg];
                mma_tf32(s[nt], aq[kk][0], aq[kk][1], aq[kk][2], aq[kk][3], b0, b1);
            }
        }
        #pragma unroll
        for (int nt = 0; nt < 8; nt++) {
            *(float2*)&SP[(wr + g) * SP_STRIDE + nt * 8 + 2 * tg]     = make_float2(s[nt][0], s[nt][1]);
            *(float2*)&SP[(wr + g + 8) * SP_STRIDE + nt * 8 + 2 * tg] = make_float2(s[nt][2], s[nt][3]);
        }
        __syncwarp();

        // online softmax (SCALE folded in here)
        {
            float* srow = SP + (wr + row_l) * SP_STRIDE + half * 32;
            const float* mrow = ma + half * 32;
            float tm = -1e30f;
            #pragma unroll
            for (int j = 0; j < 32; j++)
                tm = fmaxf(tm, fmaf(srow[j], SCALE_ATT, mrow[j]));
            tm = fmaxf(tm, __shfl_xor_sync(0xffffffffu, tm, 1));
            float m_new = fmaxf(m_run, tm);
            float fac = __expf(m_run - m_new);
            float ps = 0.f;
            #pragma unroll
            for (int j = 0; j < 32; j++) {
                float p = __expf(fmaf(srow[j], SCALE_ATT, mrow[j]) - m_new);
                ps += p;
                srow[j] = p;          // raw fp32 bits, fed to tf32 mma directly
            }
            ps += __shfl_xor_sync(0xffffffffu, ps, 1);
            l_run = l_run * fac + ps;
            m_run = m_new;
            if (half == 0) facs[wr + row_l] = fac;
        }
        __syncwarp();

        float fg  = facs[wr + g];
        float fg8 = facs[wr + g + 8];
        #pragma unroll
        for (int nt = 0; nt < 8; nt++) {
            o[nt][0] *= fg;  o[nt][1] *= fg;
            o[nt][2] *= fg8; o[nt][3] *= fg8;
        }
        #pragma unroll
        for (int kk = 0; kk < 8; kk++) {
            uint32_t a0 = SPu[(wr + g) * SP_STRIDE + kk * 8 + tg];
            uint32_t a1 = SPu[(wr + g + 8) * SP_STRIDE + kk * 8 + tg];
            uint32_t a2 = SPu[(wr + g) * SP_STRIDE + kk * 8 + 4 + tg];
            uint32_t a3 = SPu[(wr + g + 8) * SP_STRIDE + kk * 8 + 4 + tg];
            #pragma unroll
            for (int nt = 0; nt < 8; nt++) {
                uint32_t b0 = Vsu[(kk * 8 + tg) * VS_STRIDE + nt * 8 + g];
                uint32_t b1 = Vsu[(kk * 8 + tg + 4) * VS_STRIDE + nt * 8 + g];
                mma_tf32(o[nt], a0, a1, a2, a3, b0, b1);
            }
        }
    }

    if (half == 0) facs[wr + row_l] = l_run;
    __syncwarp();
    float il  = 1.0f / facs[wr + g];
    float il8 = 1.0f / facs[wr + g + 8];
    size_t r0 = ((size_t)(b * NN + brow + wr + g)) * DIMC + h * DD;
    size_t r8 = ((size_t)(b * NN + brow + wr + g + 8)) * DIMC + h * DD;
    #pragma unroll
    for (int nt = 0; nt < 8; nt++) {
        int col = nt * 8 + 2 * tg;
        *(float2*)&out[r0 + col] = make_float2(o[nt][0] * il,  o[nt][1] * il);
        *(float2*)&out[r8 + col] = make_float2(o[nt][2] * il8, o[nt][3] * il8);
    }
}

// ---------------- Launch ----------------
extern "C" void kernel_launch(void* const* d_in, const int* in_sizes, int n_in,
                              void* d_out, int out_size) {
    const float* x        = (const float*)d_in[0];
    const int*   mask     = (const int*)d_in[1];     // bool marshalled as int32
    const float* qkv_w    = (const float*)d_in[2];
    const float* CP_U_w   = (const float*)d_in[3];
    const float* CP_U_b   = (const float*)d_in[4];
    const float* CP_V_w   = (const float*)d_in[5];
    const float* CP_V_b   = (const float*)d_in[6];
    const float* CP_C     = (const float*)d_in[7];
    const float* CP_att   = (const float*)d_in[8];
    const float* proj_w   = (const float*)d_in[9];
    const float* proj_b   = (const float*)d_in[10];
    float* outp = (float*)d_out;

    float *p_qkv, *p_att, *p_WT, *p_Wc, *p_bqc, *p_bpc;
    cudaGetSymbolAddress((void**)&p_qkv, g_qkv);
    cudaGetSymbolAddress((void**)&p_att, g_att);
    cudaGetSymbolAddress((void**)&p_WT,  g_WT);
    cudaGetSymbolAddress((void**)&p_Wc,  g_Wc);
    cudaGetSymbolAddress((void**)&p_bqc, g_bqc);
    cudaGetSymbolAddress((void**)&p_bpc, g_bpc);

    static bool attr_set = false;
    if (!attr_set) {
        cudaFuncSetAttribute(attn_mma_kernel,
                             cudaFuncAttributeMaxDynamicSharedMemorySize, ATT_SMEM_BYTES);
        cudaFuncSetAttribute(gemm_nk_async,
                             cudaFuncAttributeMaxDynamicSharedMemorySize, GEMM_NK_SMEM);
        attr_set = true;
    }

    cpc_kernel<<<16, 256>>>(CP_C, CP_att);
    wfac_kernel<<<512, 256>>>(CP_V_w);
    biascomb_kernel<<<256, 256>>>(CP_U_b, CP_V_b, proj_b);

    // Fused combine: g_Wc[0..2047][512] = g_WT@CP_U_w + [qkv_w; proj_w]   K=64
    gemm_kn<<<dim3(4, 16), 256>>>(p_WT, RR, CP_U_w, RR,
                                  qkv_w, proj_w, 3 * DIMC,
                                  p_Wc, DIMC);

    // qkv = x @ Wcq^T + bqc     [8192,1536], K=512, B rows 0..1535 of g_Wc
    gemm_nk_async<<<dim3(12, MTOT / 128), 256, GEMM_NK_SMEM>>>(x, DIMC, p_Wc, DIMC,
                                                               p_bqc, p_qkv, 3 * DIMC);

    // tensor-core flash attention
    attn_mma_kernel<<<dim3(NN / 128, HH, BB), 256, ATT_SMEM_BYTES>>>(p_qkv, mask, p_att);

    // proj = att @ Wcp^T + bpc  [8192,512], K=512, B rows 1536..2047 of g_Wc
    gemm_nk_async<<<dim3(4, MTOT / 128), 256, GEMM_NK_SMEM>>>(p_att, DIMC,
                                                              p_Wc + (size_t)3 * DIMC * DIMC, DIMC,
                                                              p_bpc, outp, DIMC);
}